// round 1
// baseline (speedup 1.0000x reference)
#include <cuda_runtime.h>

#define NN 50000
#define NE 800000
#define NF 64

// Scratch: __device__ globals (no allocations allowed).
__device__ float g_dinv[NN];   // degree accumulator, then dinv = rsqrt(deg)
__device__ float g_ya[NN];     // ping
__device__ float g_yb[NN];     // pong

// y0[i] = dot(x[i,:], W[0,:]);  deg[i] = 1.0 (self-loop seed).
// One warp per node, 2 floats per lane (float2), warp shuffle reduce.
__global__ void init_kernel(const float* __restrict__ x,
                            const float* __restrict__ W) {
    __shared__ float sW[NF];
    if (threadIdx.x < NF) sW[threadIdx.x] = W[threadIdx.x];
    __syncthreads();
    int gw   = (blockIdx.x * blockDim.x + threadIdx.x) >> 5;
    int lane = threadIdx.x & 31;
    if (gw >= NN) return;
    float2 v = ((const float2*)(x + (size_t)gw * NF))[lane];
    float s = fmaf(v.x, sW[2 * lane], v.y * sW[2 * lane + 1]);
    #pragma unroll
    for (int o = 16; o; o >>= 1) s += __shfl_xor_sync(0xffffffffu, s, o);
    if (lane == 0) {
        g_ya[gw]   = s;
        g_dinv[gw] = 1.0f;   // self-loop contributes 1 to degree
    }
}

// deg[col[e]] += 1 for all edges, 4 edges per thread (int4).
__global__ void deg_kernel(const int* __restrict__ col) {
    int i = blockIdx.x * blockDim.x + threadIdx.x;
    if (i >= NE / 4) return;
    int4 c = ((const int4*)col)[i];
    atomicAdd(&g_dinv[c.x], 1.0f);
    atomicAdd(&g_dinv[c.y], 1.0f);
    atomicAdd(&g_dinv[c.z], 1.0f);
    atomicAdd(&g_dinv[c.w], 1.0f);
}

// dinv = rsqrt(deg); deg >= 1 always (self-loops), no zero guard needed.
__global__ void rsqrt_kernel() {
    int i = blockIdx.x * blockDim.x + threadIdx.x;
    if (i < NN) g_dinv[i] = rsqrtf(g_dinv[i]);
}

// Self-loop term / output init: yout[i] = dinv[i]^2 * yin[i] (+ b on last hop).
__global__ void self_kernel(const float* __restrict__ yin,
                            float* __restrict__ yout,
                            const float* __restrict__ b) {
    int i = blockIdx.x * blockDim.x + threadIdx.x;
    if (i < NN) {
        float d = g_dinv[i];
        float v = d * d * yin[i];
        if (b) v += b[0];
        yout[i] = v;
    }
}

// Edge scatter: yout[col] += dinv[row]*dinv[col]*yin[row], 4 edges per thread.
__global__ void edge_kernel(const int* __restrict__ row,
                            const int* __restrict__ col,
                            const float* __restrict__ yin,
                            float* __restrict__ yout) {
    int i = blockIdx.x * blockDim.x + threadIdx.x;
    if (i >= NE / 4) return;
    int4 r = ((const int4*)row)[i];
    int4 c = ((const int4*)col)[i];
    atomicAdd(&yout[c.x], g_dinv[r.x] * g_dinv[c.x] * yin[r.x]);
    atomicAdd(&yout[c.y], g_dinv[r.y] * g_dinv[c.y] * yin[r.y]);
    atomicAdd(&yout[c.z], g_dinv[r.z] * g_dinv[c.z] * yin[r.z]);
    atomicAdd(&yout[c.w], g_dinv[r.w] * g_dinv[c.w] * yin[r.w]);
}

extern "C" void kernel_launch(void* const* d_in, const int* in_sizes, int n_in,
                              void* d_out, int out_size) {
    const float* x  = (const float*)d_in[0];   // [NN, NF]
    const int*   ei = (const int*)d_in[1];     // [2, NE]
    const float* W  = (const float*)d_in[2];   // [1, NF]
    const float* b  = (const float*)d_in[3];   // [1]
    float* out = (float*)d_out;                // [NN, 1]

    const int* row = ei;        // edge_index[0] = sources
    const int* col = ei + NE;   // edge_index[1] = destinations

    float *ya, *yb;
    cudaGetSymbolAddress((void**)&ya, g_ya);
    cudaGetSymbolAddress((void**)&yb, g_yb);

    const int T = 256;
    const int nodeBlocks  = (NN + T - 1) / T;           // 196
    const int warpBlocks  = (NN * 32 + T - 1) / T;      // 6250 (warp per node)
    const int edgeBlocks  = (NE / 4 + T - 1) / T;       // 782

    init_kernel<<<warpBlocks, T>>>(x, W);
    deg_kernel<<<edgeBlocks, T>>>(col);
    rsqrt_kernel<<<nodeBlocks, T>>>();

    // Hop 1: ya -> yb
    self_kernel<<<nodeBlocks, T>>>(ya, yb, nullptr);
    edge_kernel<<<edgeBlocks, T>>>(row, col, ya, yb);
    // Hop 2: yb -> ya
    self_kernel<<<nodeBlocks, T>>>(yb, ya, nullptr);
    edge_kernel<<<edgeBlocks, T>>>(row, col, yb, ya);
    // Hop 3: ya -> out (fold +b into the init term; atomics then accumulate)
    self_kernel<<<nodeBlocks, T>>>(ya, out, b);
    edge_kernel<<<edgeBlocks, T>>>(row, col, ya, out);
}

// round 2
// speedup vs baseline: 1.3430x; 1.3430x over previous
#include <cuda_runtime.h>

#define NN 50000
#define NE 800000
#define NF 64
#define NE4 (NE / 4)          // 200000 quads of edges
#define TPB 256
#define WB 6250               // warp-per-node blocks: NN*32/256
#define EB ((NE4 + TPB - 1) / TPB)   // 782 edge blocks (4 edges/thread)
#define NB ((NN + TPB - 1) / TPB)    // 196 node blocks

// Scratch (__device__ globals; zero-initialized at module load).
__device__ __align__(16) float g_deg[NN];          // degree histogram (left at 0 by K5 for next call)
__device__ __align__(16) float g_norm[NE + NN];    // per-edge norm; [NE..NE+NN) = self-loop norms
__device__ __align__(16) float g_y0[NN];
__device__ __align__(16) float g_y1[NN];
__device__ __align__(16) float g_y2[NN];

// K1: fused  (a) y0[i] = x[i,:]·W  (warp per node)   (b) deg histogram over col.
__global__ void k1_init_deg(const float* __restrict__ x,
                            const float* __restrict__ W,
                            const int* __restrict__ col) {
    if (blockIdx.x < WB) {
        __shared__ float sW[NF];
        if (threadIdx.x < NF) sW[threadIdx.x] = W[threadIdx.x];
        __syncthreads();
        int gw   = (blockIdx.x * TPB + threadIdx.x) >> 5;
        int lane = threadIdx.x & 31;
        if (gw >= NN) return;
        float2 v = ((const float2*)(x + (size_t)gw * NF))[lane];
        float s = fmaf(v.x, sW[2 * lane], v.y * sW[2 * lane + 1]);
        #pragma unroll
        for (int o = 16; o; o >>= 1) s += __shfl_xor_sync(0xffffffffu, s, o);
        if (lane == 0) g_y0[gw] = s;
    } else {
        int i = (blockIdx.x - WB) * TPB + threadIdx.x;
        if (i >= NE4) return;
        int4 c = ((const int4*)col)[i];
        atomicAdd(&g_deg[c.x], 1.0f);
        atomicAdd(&g_deg[c.y], 1.0f);
        atomicAdd(&g_deg[c.z], 1.0f);
        atomicAdd(&g_deg[c.w], 1.0f);
    }
}

// K2: norm[e] = rsqrt(deg[row]+1) * rsqrt(deg[col]+1)  (self-loop folds into +1);
//     norm[NE+i] = 1/(deg[i]+1) for the implicit self edge;  y1[i] = 0.
__global__ void k2_norm(const int* __restrict__ row,
                        const int* __restrict__ col) {
    if (blockIdx.x < EB) {
        int i = blockIdx.x * TPB + threadIdx.x;
        if (i >= NE4) return;
        int4 r = ((const int4*)row)[i];
        int4 c = ((const int4*)col)[i];
        float4 n;
        n.x = rsqrtf(g_deg[r.x] + 1.0f) * rsqrtf(g_deg[c.x] + 1.0f);
        n.y = rsqrtf(g_deg[r.y] + 1.0f) * rsqrtf(g_deg[c.y] + 1.0f);
        n.z = rsqrtf(g_deg[r.z] + 1.0f) * rsqrtf(g_deg[c.z] + 1.0f);
        n.w = rsqrtf(g_deg[r.w] + 1.0f) * rsqrtf(g_deg[c.w] + 1.0f);
        ((float4*)g_norm)[i] = n;
    } else {
        int i = (blockIdx.x - EB) * TPB + threadIdx.x;
        if (i >= NN) return;
        g_norm[NE + i] = 1.0f / (g_deg[i] + 1.0f);
        g_y1[i] = 0.0f;
    }
}

// Hop kernel: edge part: yout[col] += norm[e]*yin[row] (4 edges/thread);
// node part: self edge atomicAdd + one fused aux store (zero next buffer / out=b / deg=0).
__global__ void hop_kernel(const float* __restrict__ yin,
                           float* __restrict__ yout,
                           const int* __restrict__ row,
                           const int* __restrict__ col,
                           float* __restrict__ aux,
                           const float* __restrict__ bptr) {
    if (blockIdx.x < EB) {
        int i = blockIdx.x * TPB + threadIdx.x;
        if (i >= NE4) return;
        int4 r = ((const int4*)row)[i];
        int4 c = ((const int4*)col)[i];
        float4 n = ((const float4*)g_norm)[i];
        atomicAdd(&yout[c.x], n.x * yin[r.x]);
        atomicAdd(&yout[c.y], n.y * yin[r.y]);
        atomicAdd(&yout[c.z], n.z * yin[r.z]);
        atomicAdd(&yout[c.w], n.w * yin[r.w]);
    } else {
        int i = (blockIdx.x - EB) * TPB + threadIdx.x;
        if (i >= NN) return;
        atomicAdd(&yout[i], g_norm[NE + i] * yin[i]);
        aux[i] = bptr ? bptr[0] : 0.0f;
    }
}

extern "C" void kernel_launch(void* const* d_in, const int* in_sizes, int n_in,
                              void* d_out, int out_size) {
    const float* x  = (const float*)d_in[0];   // [NN, NF]
    const int*   ei = (const int*)d_in[1];     // [2, NE]
    const float* W  = (const float*)d_in[2];   // [1, NF]
    const float* b  = (const float*)d_in[3];   // [1]
    float* out = (float*)d_out;                // [NN]

    const int* row = ei;        // sources
    const int* col = ei + NE;   // destinations

    float *y0, *y1, *y2, *deg;
    cudaGetSymbolAddress((void**)&y0, g_y0);
    cudaGetSymbolAddress((void**)&y1, g_y1);
    cudaGetSymbolAddress((void**)&y2, g_y2);
    cudaGetSymbolAddress((void**)&deg, g_deg);

    // K1: y0 = x·W  +  deg histogram            (deg starts at 0: zeroed by prev call / load-init)
    k1_init_deg<<<WB + EB, TPB>>>(x, W, col);
    // K2: per-edge norms + self norms; zero y1
    k2_norm<<<EB + NB, TPB>>>(row, col);
    // Hop 1: y0 -> y1;  zero y2
    hop_kernel<<<EB + NB, TPB>>>(y0, y1, row, col, y2, nullptr);
    // Hop 2: y1 -> y2;  out = b (init before hop-3 atomics)
    hop_kernel<<<EB + NB, TPB>>>(y1, y2, row, col, out, b);
    // Hop 3: y2 -> out; zero deg for the next replay
    hop_kernel<<<EB + NB, TPB>>>(y2, out, row, col, deg, nullptr);
}